// round 1
// baseline (speedup 1.0000x reference)
#include <cuda_runtime.h>
#include <cuda_bf16.h>
#include <math_constants.h>

// Problem constants (reference: N=100000, E=1200000, all dims 128)
#define MAXN 100000
#define MAXE 1200000
#define MAXE2 (MAXE + MAXN)

// Scratch (device globals — allocation-free rule)
__device__ __align__(16) float g_xw[MAXN * 128];     // x @ W            [N,128]
__device__ __align__(16) float g_h[MAXN * 128];      // layer output     [N,128]
__device__ __align__(16) float g_out[MAXN * 128];    // aggregation acc  [N,128]
__device__ __align__(16) float g_ssrc[MAXN * 4];
__device__ __align__(16) float g_sdst[MAXN * 4];
__device__ __align__(16) float g_amax[MAXN * 4];
__device__ __align__(16) float g_denom[MAXN * 4];
__device__ __align__(16) float g_alpha[MAXE2 * 4];   // leaky-relu scores, then reused as ex

// ---------------------------------------------------------------------------
// GEMM: C[n,128] = A[n,128] @ W[128,128], C -> g_xw
// Block: 256 threads, tile 64 rows x 128 cols, full W in smem.
// ---------------------------------------------------------------------------
__global__ __launch_bounds__(256) void gemm128_k(
    const float* __restrict__ A, const float* __restrict__ W, int n)
{
    extern __shared__ float sm[];
    float4* sA4 = (float4*)sm;            // 64 x 32 float4
    float4* sW4 = (float4*)(sm + 64 * 128); // 128 x 32 float4

    int t = threadIdx.x;
    int row0 = blockIdx.x * 64;

    const float4* A4 = (const float4*)A;
    #pragma unroll
    for (int i = 0; i < 8; i++) {
        int idx = t + i * 256;          // 0..2047
        int r = idx >> 5, c = idx & 31;
        float4 v = make_float4(0.f, 0.f, 0.f, 0.f);
        if (row0 + r < n) v = A4[(size_t)(row0 + r) * 32 + c];
        sA4[idx] = v;
    }
    const float4* W4 = (const float4*)W;
    #pragma unroll
    for (int i = 0; i < 16; i++) {
        int idx = t + i * 256;          // 0..4095
        sW4[idx] = W4[idx];
    }
    __syncthreads();

    int tx = t & 31, ty = t >> 5;       // tx: col-group (4 cols), ty: row sub
    float4 acc[8];
    #pragma unroll
    for (int i = 0; i < 8; i++) acc[i] = make_float4(0.f, 0.f, 0.f, 0.f);

    #pragma unroll
    for (int k4 = 0; k4 < 32; k4++) {
        float4 w0 = sW4[(4 * k4 + 0) * 32 + tx];
        float4 w1 = sW4[(4 * k4 + 1) * 32 + tx];
        float4 w2 = sW4[(4 * k4 + 2) * 32 + tx];
        float4 w3 = sW4[(4 * k4 + 3) * 32 + tx];
        #pragma unroll
        for (int i = 0; i < 8; i++) {
            float4 a = sA4[(i * 8 + ty) * 32 + k4];
            acc[i].x = fmaf(a.x, w0.x, fmaf(a.y, w1.x, fmaf(a.z, w2.x, fmaf(a.w, w3.x, acc[i].x))));
            acc[i].y = fmaf(a.x, w0.y, fmaf(a.y, w1.y, fmaf(a.z, w2.y, fmaf(a.w, w3.y, acc[i].y))));
            acc[i].z = fmaf(a.x, w0.z, fmaf(a.y, w1.z, fmaf(a.z, w2.z, fmaf(a.w, w3.z, acc[i].z))));
            acc[i].w = fmaf(a.x, w0.w, fmaf(a.y, w1.w, fmaf(a.z, w2.w, fmaf(a.w, w3.w, acc[i].w))));
        }
    }

    float4* O4 = (float4*)g_xw;
    #pragma unroll
    for (int i = 0; i < 8; i++) {
        int r = row0 + i * 8 + ty;
        if (r < n) O4[(size_t)r * 32 + tx] = acc[i];
    }
}

// ---------------------------------------------------------------------------
// Per-node attention halves + init of amax/denom/out. One warp per node.
// ---------------------------------------------------------------------------
__global__ void score_init_k(const float* __restrict__ as,
                             const float* __restrict__ ad, int n)
{
    int gid = blockIdx.x * blockDim.x + threadIdx.x;
    int node = gid >> 5, lane = gid & 31;
    if (node >= n) return;

    float4 v = *(const float4*)(g_xw + (size_t)node * 128 + lane * 4);
    float4 a = *(const float4*)(as + lane * 4);
    float4 b = *(const float4*)(ad + lane * 4);
    float ps = v.x * a.x + v.y * a.y + v.z * a.z + v.w * a.w;
    float pd = v.x * b.x + v.y * b.y + v.z * b.z + v.w * b.w;

    // reduce within each 8-lane group (one head per group)
    ps += __shfl_down_sync(0xffffffffu, ps, 4);
    ps += __shfl_down_sync(0xffffffffu, ps, 2);
    ps += __shfl_down_sync(0xffffffffu, ps, 1);
    pd += __shfl_down_sync(0xffffffffu, pd, 4);
    pd += __shfl_down_sync(0xffffffffu, pd, 2);
    pd += __shfl_down_sync(0xffffffffu, pd, 1);

    if ((lane & 7) == 0) {
        int h = lane >> 3;
        g_ssrc[node * 4 + h] = ps;
        g_sdst[node * 4 + h] = pd;
        g_amax[node * 4 + h] = __int_as_float(0xff800000);  // -inf
        g_denom[node * 4 + h] = 0.f;
    }
    *(float4*)(g_out + (size_t)node * 128 + lane * 4) = make_float4(0.f, 0.f, 0.f, 0.f);
}

__device__ __forceinline__ void atomicMaxF(float* addr, float v) {
    if (v >= 0.f) atomicMax((int*)addr, __float_as_int(v));
    else          atomicMin((unsigned int*)addr, __float_as_uint(v));
}

// ---------------------------------------------------------------------------
// Pass 1: alpha = leaky_relu(s_src[src]+s_dst[dst]); segment max via atomics.
// One thread per edge (4 heads each).
// ---------------------------------------------------------------------------
__global__ void edge_max_k(const int* __restrict__ ei, int E, int E2)
{
    int e = blockIdx.x * blockDim.x + threadIdx.x;
    if (e >= E2) return;
    int s, d;
    if (e < E) { s = __ldg(ei + e); d = __ldg(ei + E + e); }
    else       { s = d = e - E; }

    float4 ss = *(const float4*)(g_ssrc + (size_t)s * 4);
    float4 sd = *(const float4*)(g_sdst + (size_t)d * 4);
    float4 a;
    a.x = ss.x + sd.x; a.x = a.x > 0.f ? a.x : 0.2f * a.x;
    a.y = ss.y + sd.y; a.y = a.y > 0.f ? a.y : 0.2f * a.y;
    a.z = ss.z + sd.z; a.z = a.z > 0.f ? a.z : 0.2f * a.z;
    a.w = ss.w + sd.w; a.w = a.w > 0.f ? a.w : 0.2f * a.w;
    *(float4*)(g_alpha + (size_t)e * 4) = a;

    float* am = g_amax + (size_t)d * 4;
    atomicMaxF(am + 0, a.x);
    atomicMaxF(am + 1, a.y);
    atomicMaxF(am + 2, a.z);
    atomicMaxF(am + 3, a.w);
}

// ---------------------------------------------------------------------------
// Pass 2: ex = exp(alpha - amax[dst]); denom[dst] += ex. Stores ex over alpha.
// ---------------------------------------------------------------------------
__global__ void edge_exp_k(const int* __restrict__ ei, int E, int E2)
{
    int e = blockIdx.x * blockDim.x + threadIdx.x;
    if (e >= E2) return;
    int d = (e < E) ? __ldg(ei + E + e) : (e - E);

    float4 a = *(const float4*)(g_alpha + (size_t)e * 4);
    float4 m = *(const float4*)(g_amax + (size_t)d * 4);
    float4 ex;
    ex.x = expf(a.x - m.x);
    ex.y = expf(a.y - m.y);
    ex.z = expf(a.z - m.z);
    ex.w = expf(a.w - m.w);
    *(float4*)(g_alpha + (size_t)e * 4) = ex;

#if __CUDA_ARCH__ >= 900
    atomicAdd((float4*)(g_denom + (size_t)d * 4), ex);
#else
    atomicAdd(g_denom + d * 4 + 0, ex.x);
    atomicAdd(g_denom + d * 4 + 1, ex.y);
    atomicAdd(g_denom + d * 4 + 2, ex.z);
    atomicAdd(g_denom + d * 4 + 3, ex.w);
#endif
}

// ---------------------------------------------------------------------------
// Pass 3: out[dst] += xw[src] * attn. One warp per edge; lane covers 4 feats.
// ---------------------------------------------------------------------------
__global__ void edge_agg_k(const int* __restrict__ ei, int E, int E2)
{
    long long gid = (long long)blockIdx.x * blockDim.x + threadIdx.x;
    int e = (int)(gid >> 5);
    int lane = (int)(gid & 31);
    if (e >= E2) return;
    int s, d;
    if (e < E) { s = __ldg(ei + e); d = __ldg(ei + E + e); }
    else       { s = d = e - E; }

    int h = lane >> 3;  // lane*4 .. lane*4+3 all inside head h
    float ex  = g_alpha[(size_t)e * 4 + h];
    float den = g_denom[(size_t)d * 4 + h];
    float attn = ex / fmaxf(den, 1e-16f);

    float4 v = *(const float4*)(g_xw + (size_t)s * 128 + lane * 4);
    float4 msg = make_float4(v.x * attn, v.y * attn, v.z * attn, v.w * attn);

    float* o = g_out + (size_t)d * 128 + lane * 4;
#if __CUDA_ARCH__ >= 900
    atomicAdd((float4*)o, msg);
#else
    atomicAdd(o + 0, msg.x);
    atomicAdd(o + 1, msg.y);
    atomicAdd(o + 2, msg.z);
    atomicAdd(o + 3, msg.w);
#endif
}

// ---------------------------------------------------------------------------
// Finalize layers 1/2: h = elu(out + b)
// ---------------------------------------------------------------------------
__global__ void final12_k(const float* __restrict__ b, int n)
{
    int i = blockIdx.x * blockDim.x + threadIdx.x;
    if (i >= n * 128) return;
    float v = g_out[i] + __ldg(b + (i & 127));
    g_h[i] = v > 0.f ? v : (expf(v) - 1.f);
}

// ---------------------------------------------------------------------------
// Finalize layer 3: out = mean over heads + b3
// ---------------------------------------------------------------------------
__global__ void final3_k(const float* __restrict__ b3, float* __restrict__ out, int n)
{
    int i = blockIdx.x * blockDim.x + threadIdx.x;
    if (i >= n * 32) return;
    int node = i >> 5, c = i & 31;
    const float* o = g_out + (size_t)node * 128;
    out[i] = 0.25f * (o[c] + o[c + 32] + o[c + 64] + o[c + 96]) + __ldg(b3 + c);
}

// ---------------------------------------------------------------------------
extern "C" void kernel_launch(void* const* d_in, const int* in_sizes, int n_in,
                              void* d_out, int out_size)
{
    const float* x  = (const float*)d_in[0];
    const int*   ei = (const int*)d_in[1];
    const float* W[3]  = {(const float*)d_in[2], (const float*)d_in[6],  (const float*)d_in[10]};
    const float* AS[3] = {(const float*)d_in[3], (const float*)d_in[7],  (const float*)d_in[11]};
    const float* AD[3] = {(const float*)d_in[4], (const float*)d_in[8],  (const float*)d_in[12]};
    const float* B[3]  = {(const float*)d_in[5], (const float*)d_in[9],  (const float*)d_in[13]};

    int n  = in_sizes[0] / 128;
    int E  = in_sizes[1] / 2;
    int E2 = E + n;

    float* hbuf = nullptr;
    cudaGetSymbolAddress((void**)&hbuf, g_h);

    const int SMEM = (64 * 128 + 128 * 128) * (int)sizeof(float);  // 96 KB
    cudaFuncSetAttribute(gemm128_k, cudaFuncAttributeMaxDynamicSharedMemorySize, SMEM);

    const float* in = x;
    for (int L = 0; L < 3; L++) {
        gemm128_k<<<(n + 63) / 64, 256, SMEM>>>(in, W[L], n);
        score_init_k<<<(n * 32 + 255) / 256, 256>>>(AS[L], AD[L], n);
        edge_max_k<<<(E2 + 255) / 256, 256>>>(ei, E, E2);
        edge_exp_k<<<(E2 + 255) / 256, 256>>>(ei, E, E2);
        long long agg_threads = (long long)E2 * 32;
        edge_agg_k<<<(unsigned)((agg_threads + 255) / 256), 256>>>(ei, E, E2);
        if (L < 2) {
            final12_k<<<(n * 128 + 255) / 256, 256>>>(B[L], n);
            in = hbuf;
        } else {
            final3_k<<<(n * 32 + 255) / 256, 256>>>(B[2], (float*)d_out, n);
        }
    }
}

// round 2
// speedup vs baseline: 2.7862x; 2.7862x over previous
#include <cuda_runtime.h>
#include <cuda_bf16.h>
#include <math_constants.h>

// Problem constants (reference: N=100000, E=1200000, all dims 128)
#define MAXN 100000
#define MAXE 1200000
#define MAXE2 (MAXE + MAXN)

// Scratch (device globals — allocation-free rule)
__device__ __align__(16) float g_xw[MAXN * 128];     // x @ W            [N,128]
__device__ __align__(16) float g_h[MAXN * 128];      // layer output     [N,128]
__device__ __align__(16) float g_ssrc[MAXN * 4];
__device__ __align__(16) float g_sdst[MAXN * 4];
__device__ __align__(16) float g_alpha[MAXE2 * 4];   // per-(CSR-slot,head) scores/weights

__device__ int g_counts[MAXN];
__device__ int g_cursor[MAXN];
__device__ int g_rowptr[MAXN + 1];
__device__ int g_csr[MAXE2];                          // src per CSR slot (dst-sorted)

// ---------------------------------------------------------------------------
// GEMM: C[n,128] = A[n,128] @ W[128,128], C -> g_xw
// ---------------------------------------------------------------------------
__global__ __launch_bounds__(256) void gemm128_k(
    const float* __restrict__ A, const float* __restrict__ W, int n)
{
    extern __shared__ float sm[];
    float4* sA4 = (float4*)sm;               // 64 x 32 float4
    float4* sW4 = (float4*)(sm + 64 * 128);  // 128 x 32 float4

    int t = threadIdx.x;
    int row0 = blockIdx.x * 64;

    const float4* A4 = (const float4*)A;
    #pragma unroll
    for (int i = 0; i < 8; i++) {
        int idx = t + i * 256;
        int r = idx >> 5, c = idx & 31;
        float4 v = make_float4(0.f, 0.f, 0.f, 0.f);
        if (row0 + r < n) v = A4[(size_t)(row0 + r) * 32 + c];
        sA4[idx] = v;
    }
    const float4* W4 = (const float4*)W;
    #pragma unroll
    for (int i = 0; i < 16; i++) {
        int idx = t + i * 256;
        sW4[idx] = W4[idx];
    }
    __syncthreads();

    int tx = t & 31, ty = t >> 5;
    float4 acc[8];
    #pragma unroll
    for (int i = 0; i < 8; i++) acc[i] = make_float4(0.f, 0.f, 0.f, 0.f);

    #pragma unroll
    for (int k4 = 0; k4 < 32; k4++) {
        float4 w0 = sW4[(4 * k4 + 0) * 32 + tx];
        float4 w1 = sW4[(4 * k4 + 1) * 32 + tx];
        float4 w2 = sW4[(4 * k4 + 2) * 32 + tx];
        float4 w3 = sW4[(4 * k4 + 3) * 32 + tx];
        #pragma unroll
        for (int i = 0; i < 8; i++) {
            float4 a = sA4[(i * 8 + ty) * 32 + k4];
            acc[i].x = fmaf(a.x, w0.x, fmaf(a.y, w1.x, fmaf(a.z, w2.x, fmaf(a.w, w3.x, acc[i].x))));
            acc[i].y = fmaf(a.x, w0.y, fmaf(a.y, w1.y, fmaf(a.z, w2.y, fmaf(a.w, w3.y, acc[i].y))));
            acc[i].z = fmaf(a.x, w0.z, fmaf(a.y, w1.z, fmaf(a.z, w2.z, fmaf(a.w, w3.z, acc[i].z))));
            acc[i].w = fmaf(a.x, w0.w, fmaf(a.y, w1.w, fmaf(a.z, w2.w, fmaf(a.w, w3.w, acc[i].w))));
        }
    }

    float4* O4 = (float4*)g_xw;
    #pragma unroll
    for (int i = 0; i < 8; i++) {
        int r = row0 + i * 8 + ty;
        if (r < n) O4[(size_t)r * 32 + tx] = acc[i];
    }
}

// ---------------------------------------------------------------------------
// Per-node attention halves. One warp per node.
// ---------------------------------------------------------------------------
__global__ void score_init_k(const float* __restrict__ as,
                             const float* __restrict__ ad, int n)
{
    int gid = blockIdx.x * blockDim.x + threadIdx.x;
    int node = gid >> 5, lane = gid & 31;
    if (node >= n) return;

    float4 v = *(const float4*)(g_xw + (size_t)node * 128 + lane * 4);
    float4 a = *(const float4*)(as + lane * 4);
    float4 b = *(const float4*)(ad + lane * 4);
    float ps = v.x * a.x + v.y * a.y + v.z * a.z + v.w * a.w;
    float pd = v.x * b.x + v.y * b.y + v.z * b.z + v.w * b.w;

    ps += __shfl_down_sync(0xffffffffu, ps, 4);
    ps += __shfl_down_sync(0xffffffffu, ps, 2);
    ps += __shfl_down_sync(0xffffffffu, ps, 1);
    pd += __shfl_down_sync(0xffffffffu, pd, 4);
    pd += __shfl_down_sync(0xffffffffu, pd, 2);
    pd += __shfl_down_sync(0xffffffffu, pd, 1);

    if ((lane & 7) == 0) {
        int h = lane >> 3;
        g_ssrc[node * 4 + h] = ps;
        g_sdst[node * 4 + h] = pd;
    }
}

// ---------------------------------------------------------------------------
// CSR build (once per launch; edge structure identical across layers)
// ---------------------------------------------------------------------------
__global__ void hist_k(const int* __restrict__ ei, int E, int E2)
{
    int e = blockIdx.x * blockDim.x + threadIdx.x;
    if (e >= E2) return;
    int d = (e < E) ? __ldg(ei + E + e) : (e - E);
    atomicAdd(g_counts + d, 1);
}

// Single-block scan over counts -> rowptr (exclusive, n+1) and cursor.
__global__ __launch_bounds__(1024) void scan_k(int n, int E2)
{
    __shared__ int warpsums[32];
    __shared__ int s_carry;
    int lane = threadIdx.x & 31, wid = threadIdx.x >> 5;
    if (threadIdx.x == 0) s_carry = 0;
    __syncthreads();

    for (int base = 0; base < n; base += 1024) {
        int i = base + threadIdx.x;
        int v = (i < n) ? g_counts[i] : 0;
        int x = v;
        #pragma unroll
        for (int off = 1; off < 32; off <<= 1) {
            int t = __shfl_up_sync(0xffffffffu, x, off);
            if (lane >= off) x += t;
        }
        if (lane == 31) warpsums[wid] = x;
        __syncthreads();
        if (wid == 0) {
            int ws = warpsums[lane];
            #pragma unroll
            for (int off = 1; off < 32; off <<= 1) {
                int t = __shfl_up_sync(0xffffffffu, ws, off);
                if (lane >= off) ws += t;
            }
            warpsums[lane] = ws;
        }
        __syncthreads();
        int incl = x + (wid > 0 ? warpsums[wid - 1] : 0);
        int carry = s_carry;
        if (i < n) {
            g_rowptr[i + 1] = carry + incl;
            g_cursor[i] = carry + incl - v;
        }
        __syncthreads();
        if (threadIdx.x == 1023) s_carry = carry + warpsums[31];
        __syncthreads();
    }
    if (threadIdx.x == 0) { g_rowptr[0] = 0; g_rowptr[n] = E2; }
}

__global__ void scatter_k(const int* __restrict__ ei, int E, int E2)
{
    int e = blockIdx.x * blockDim.x + threadIdx.x;
    if (e >= E2) return;
    int s, d;
    if (e < E) { s = __ldg(ei + e); d = __ldg(ei + E + e); }
    else       { s = d = e - E; }
    int pos = atomicAdd(g_cursor + d, 1);
    g_csr[pos] = s;
}

// ---------------------------------------------------------------------------
// Fused per-destination softmax + aggregation + epilogue. One warp per node.
// mode 0: out = elu(agg + bias), [N,128]   mode 1: out = mean_heads(agg)+b3, [N,32]
// ---------------------------------------------------------------------------
__global__ __launch_bounds__(256) void fused_gat_k(
    const float* __restrict__ bias, float* __restrict__ out, int n, int mode)
{
    int gid = blockIdx.x * blockDim.x + threadIdx.x;
    int node = gid >> 5, lane = gid & 31;
    if (node >= n) return;

    int beg = g_rowptr[node];
    int end = g_rowptr[node + 1];

    float4 sd = *(const float4*)(g_sdst + (size_t)node * 4);

    // Phase A: scores + per-head max
    const float NINF = __int_as_float(0xff800000);
    float4 m = make_float4(NINF, NINF, NINF, NINF);
    for (int j = beg + lane; j < end; j += 32) {
        int s = g_csr[j];
        float4 ss = *(const float4*)(g_ssrc + (size_t)s * 4);
        float4 a;
        a.x = ss.x + sd.x; a.x = a.x > 0.f ? a.x : 0.2f * a.x;
        a.y = ss.y + sd.y; a.y = a.y > 0.f ? a.y : 0.2f * a.y;
        a.z = ss.z + sd.z; a.z = a.z > 0.f ? a.z : 0.2f * a.z;
        a.w = ss.w + sd.w; a.w = a.w > 0.f ? a.w : 0.2f * a.w;
        *(float4*)(g_alpha + (size_t)j * 4) = a;
        m.x = fmaxf(m.x, a.x); m.y = fmaxf(m.y, a.y);
        m.z = fmaxf(m.z, a.z); m.w = fmaxf(m.w, a.w);
    }
    #pragma unroll
    for (int off = 16; off > 0; off >>= 1) {
        m.x = fmaxf(m.x, __shfl_xor_sync(0xffffffffu, m.x, off));
        m.y = fmaxf(m.y, __shfl_xor_sync(0xffffffffu, m.y, off));
        m.z = fmaxf(m.z, __shfl_xor_sync(0xffffffffu, m.z, off));
        m.w = fmaxf(m.w, __shfl_xor_sync(0xffffffffu, m.w, off));
    }

    // Phase B: exp + per-head denom
    float4 den = make_float4(0.f, 0.f, 0.f, 0.f);
    for (int j = beg + lane; j < end; j += 32) {
        float4 a = *(const float4*)(g_alpha + (size_t)j * 4);
        float4 ex;
        ex.x = expf(a.x - m.x);
        ex.y = expf(a.y - m.y);
        ex.z = expf(a.z - m.z);
        ex.w = expf(a.w - m.w);
        *(float4*)(g_alpha + (size_t)j * 4) = ex;
        den.x += ex.x; den.y += ex.y; den.z += ex.z; den.w += ex.w;
    }
    #pragma unroll
    for (int off = 16; off > 0; off >>= 1) {
        den.x += __shfl_xor_sync(0xffffffffu, den.x, off);
        den.y += __shfl_xor_sync(0xffffffffu, den.y, off);
        den.z += __shfl_xor_sync(0xffffffffu, den.z, off);
        den.w += __shfl_xor_sync(0xffffffffu, den.w, off);
    }

    int h = lane >> 3;  // lane's 4 features all belong to head h
    float den_h = (h == 0) ? den.x : (h == 1) ? den.y : (h == 2) ? den.z : den.w;
    float inv = 1.0f / fmaxf(den_h, 1e-16f);

    // Phase C: weighted aggregation (coalesced 512B gather per neighbor)
    float4 acc = make_float4(0.f, 0.f, 0.f, 0.f);
    #pragma unroll 4
    for (int j = beg; j < end; j++) {
        int s = g_csr[j];                              // warp-uniform broadcast
        float at = g_alpha[(size_t)j * 4 + h] * inv;   // 8-way broadcast
        float4 v = *(const float4*)(g_xw + (size_t)s * 128 + lane * 4);
        acc.x = fmaf(v.x, at, acc.x);
        acc.y = fmaf(v.y, at, acc.y);
        acc.z = fmaf(v.z, at, acc.z);
        acc.w = fmaf(v.w, at, acc.w);
    }

    if (mode == 0) {
        float4 b = *(const float4*)(bias + lane * 4);
        float4 o;
        o.x = acc.x + b.x; o.x = o.x > 0.f ? o.x : (expf(o.x) - 1.f);
        o.y = acc.y + b.y; o.y = o.y > 0.f ? o.y : (expf(o.y) - 1.f);
        o.z = acc.z + b.z; o.z = o.z > 0.f ? o.z : (expf(o.z) - 1.f);
        o.w = acc.w + b.w; o.w = o.w > 0.f ? o.w : (expf(o.w) - 1.f);
        *(float4*)(out + (size_t)node * 128 + lane * 4) = o;
    } else {
        // mean over 4 heads: lanes {l, l^8, l^16, l^24} hold same feature group
        acc.x += __shfl_xor_sync(0xffffffffu, acc.x, 8);
        acc.y += __shfl_xor_sync(0xffffffffu, acc.y, 8);
        acc.z += __shfl_xor_sync(0xffffffffu, acc.z, 8);
        acc.w += __shfl_xor_sync(0xffffffffu, acc.w, 8);
        acc.x += __shfl_xor_sync(0xffffffffu, acc.x, 16);
        acc.y += __shfl_xor_sync(0xffffffffu, acc.y, 16);
        acc.z += __shfl_xor_sync(0xffffffffu, acc.z, 16);
        acc.w += __shfl_xor_sync(0xffffffffu, acc.w, 16);
        if (lane < 8) {
            float4 b = *(const float4*)(bias + lane * 4);
            float4 o;
            o.x = 0.25f * acc.x + b.x;
            o.y = 0.25f * acc.y + b.y;
            o.z = 0.25f * acc.z + b.z;
            o.w = 0.25f * acc.w + b.w;
            *(float4*)(out + (size_t)node * 32 + lane * 4) = o;
        }
    }
}

// ---------------------------------------------------------------------------
extern "C" void kernel_launch(void* const* d_in, const int* in_sizes, int n_in,
                              void* d_out, int out_size)
{
    const float* x  = (const float*)d_in[0];
    const int*   ei = (const int*)d_in[1];
    const float* W[3]  = {(const float*)d_in[2], (const float*)d_in[6],  (const float*)d_in[10]};
    const float* AS[3] = {(const float*)d_in[3], (const float*)d_in[7],  (const float*)d_in[11]};
    const float* AD[3] = {(const float*)d_in[4], (const float*)d_in[8],  (const float*)d_in[12]};
    const float* B[3]  = {(const float*)d_in[5], (const float*)d_in[9],  (const float*)d_in[13]};

    int n  = in_sizes[0] / 128;
    int E  = in_sizes[1] / 2;
    int E2 = E + n;

    float* hbuf = nullptr;
    cudaGetSymbolAddress((void**)&hbuf, g_h);
    int* counts_ptr = nullptr;
    cudaGetSymbolAddress((void**)&counts_ptr, g_counts);

    const int SMEM = (64 * 128 + 128 * 128) * (int)sizeof(float);  // 96 KB
    cudaFuncSetAttribute(gemm128_k, cudaFuncAttributeMaxDynamicSharedMemorySize, SMEM);

    // CSR build (edge structure shared by all 3 layers)
    cudaMemsetAsync(counts_ptr, 0, (size_t)n * sizeof(int));
    hist_k<<<(E2 + 255) / 256, 256>>>(ei, E, E2);
    scan_k<<<1, 1024>>>(n, E2);
    scatter_k<<<(E2 + 255) / 256, 256>>>(ei, E, E2);

    const float* in = x;
    for (int L = 0; L < 3; L++) {
        gemm128_k<<<(n + 63) / 64, 256, SMEM>>>(in, W[L], n);
        score_init_k<<<(n * 32 + 255) / 256, 256>>>(AS[L], AD[L], n);
        if (L < 2) {
            fused_gat_k<<<(n * 32 + 255) / 256, 256>>>(B[L], hbuf, n, 0);
            in = hbuf;
        } else {
            fused_gat_k<<<(n * 32 + 255) / 256, 256>>>(B[2], (float*)d_out, n, 1);
        }
    }
}